// round 13
// baseline (speedup 1.0000x reference)
#include <cuda_runtime.h>
#include <cuda_bf16.h>

// Problem constants (fixed shapes from reference)
#define B_     128
#define C_     1024
#define HW_    196          // 14*14
#define VEC_   49           // 196/4 float4 per channel row
#define CHUNKS 16           // channel chunks per sample
#define CPB    64           // channels per block (C_/CHUNKS)
#define THREADS 256         // 8 warps
#define NPART  (B_*CHUNKS)  // 2048 partials (one per block)

#define MARGIN 1.0f
#define EPS    1e-6f

__device__ float g_partials[NPART];
__device__ unsigned int g_ticket = 0;   // self-resetting; replay-safe

// minBlocks=4 -> ptxas register cap 64/thread -> full 32-warp occupancy is
// still possible while keeping an 8-deep float4 load batch live (MLP ~8).
__global__ __launch_bounds__(THREADS, 4)
void ffl_fused_kernel(const float* __restrict__ feat,
                      const float* __restrict__ feat_p,
                      const float* __restrict__ avg_feat,   // [2,1024]
                      const int* __restrict__ qual,         // [128] int32
                      const int* __restrict__ label,        // [128] int32
                      float* __restrict__ out)
{
    const int chunk = blockIdx.x;        // 0..15
    const int b     = blockIdx.y;        // 0..127
    const int tid   = threadIdx.x;
    const int warp  = tid >> 5;          // 0..7
    const int lane  = tid & 31;

    // Select source tensor for this sample (only this one is read)
    const int q  = qual[b];
    const float* __restrict__ src = (q == 1) ? feat : feat_p;
    const int lb = label[b] & 1;   // mask: guaranteed in-bounds gather
    const float* __restrict__ af_pos = avg_feat + (size_t)lb * C_;
    const float* __restrict__ af_neg = avg_feat + (size_t)(1 - lb) * C_;

    // This warp owns 8 contiguous channels: cbase .. cbase+7
    const int cbase = chunk * CPB + warp * 8;
    const float4* __restrict__ base =
        reinterpret_cast<const float4*>(src + ((size_t)b * C_ + cbase) * HW_);

    const bool tail = (lane < VEC_ - 32);   // lanes 0..16 load the second vec

    // ---- Batch 1: 8 independent streaming LDG.128, then sum ----
    float4 v[8];
    #pragma unroll
    for (int r = 0; r < 8; ++r)
        v[r] = __ldcs(base + (size_t)r * VEC_ + lane);

    float s[8];
    #pragma unroll
    for (int r = 0; r < 8; ++r)
        s[r] = (v[r].x + v[r].y) + (v[r].z + v[r].w);

    // ---- Batch 2: 8 predicated tail LDG.128 (lanes 0..16), then add ----
    #pragma unroll
    for (int r = 0; r < 8; ++r)
        if (tail) v[r] = __ldcs(base + (size_t)r * VEC_ + lane + 32);

    #pragma unroll
    for (int r = 0; r < 8; ++r)
        if (tail) s[r] += (v[r].x + v[r].y) + (v[r].z + v[r].w);

    // ---- 8 independent butterfly reductions (pipelined) ----
    #pragma unroll
    for (int off = 16; off > 0; off >>= 1) {
        #pragma unroll
        for (int r = 0; r < 8; ++r)
            s[r] += __shfl_xor_sync(0xFFFFFFFFu, s[r], off);
    }

    float acc = 0.0f;
    if (lane == 0) {
        #pragma unroll
        for (int r = 0; r < 8; ++r) {
            const int   c   = cbase + r;
            const float sel = s[r] * (1.0f / (float)HW_);
            acc += fmaxf(fabsf(sel - af_pos[c] + EPS)
                       - fabsf(sel - af_neg[c] + EPS) + MARGIN, 0.0f);
        }
    }

    // Block reduce the 8 warp-leader partials (fixed order -> deterministic)
    __shared__ float warp_acc[8];
    __shared__ bool  is_last;
    if (lane == 0) warp_acc[warp] = acc;
    __syncthreads();
    if (tid == 0) {
        float t = 0.0f;
        #pragma unroll
        for (int w = 0; w < 8; ++w) t += warp_acc[w];
        __stcg(&g_partials[b * CHUNKS + chunk], t * (1.0f / (float)C_));
        __threadfence();
        unsigned int ticket = atomicAdd(&g_ticket, 1u);
        is_last = (ticket == NPART - 1);
    }
    __syncthreads();

    // Last block to finish performs the deterministic final sum.
    if (is_last) {
        if (tid == 0) g_ticket = 0;   // reset for next graph replay
        float s2 = 0.0f;
        #pragma unroll
        for (int i = 0; i < NPART / THREADS; ++i)       // 8 each, fixed order
            s2 += __ldcg(&g_partials[tid + i * THREADS]);

        __shared__ float sm[THREADS];
        sm[tid] = s2;
        __syncthreads();
        #pragma unroll
        for (int step = THREADS / 2; step > 0; step >>= 1) {
            if (tid < step) sm[tid] += sm[tid + step];
            __syncthreads();
        }
        if (tid == 0) out[0] = sm[0];
    }
}

extern "C" void kernel_launch(void* const* d_in, const int* in_sizes, int n_in,
                              void* d_out, int out_size)
{
    const float* feat     = (const float*)d_in[0];
    const float* feat_p   = (const float*)d_in[1];
    const float* avg_feat = (const float*)d_in[2];
    const int*   qual     = (const int*)d_in[3];
    const int*   label    = (const int*)d_in[4];
    float* out = (float*)d_out;

    dim3 grid(CHUNKS, B_);
    ffl_fused_kernel<<<grid, THREADS>>>(feat, feat_p, avg_feat, qual, label, out);
}

// round 14
// speedup vs baseline: 1.4377x; 1.4377x over previous
#include <cuda_runtime.h>
#include <cuda_bf16.h>

// Problem constants (fixed shapes from reference)
#define B_     128
#define C_     1024
#define HW_    196          // 14*14
#define VEC_   49           // 196/4 float4 per channel row
#define CHUNKS 8            // channel chunks per sample (single-wave grid: 8*128=1024 blocks)
#define CPB    128          // channels per block (C_/CHUNKS)
#define THREADS 256         // 8 warps
#define NPART  (B_*CHUNKS)  // 1024 partials (one per block)

#define MARGIN 1.0f
#define EPS    1e-6f

__device__ float g_partials[NPART];
__device__ unsigned int g_ticket = 0;   // self-resetting; replay-safe

// minBlocks=8 -> ptxas register cap 32/thread -> full 2048-thread occupancy
// (the measured-fastest operating point; MLP ladder was a dead end).
__global__ __launch_bounds__(THREADS, 8)
void ffl_fused_kernel(const float* __restrict__ feat,
                      const float* __restrict__ feat_p,
                      const float* __restrict__ avg_feat,   // [2,1024]
                      const int* __restrict__ qual,         // [128] int32
                      const int* __restrict__ label,        // [128] int32
                      float* __restrict__ out)
{
    const int chunk = blockIdx.x;        // 0..7
    const int b     = blockIdx.y;        // 0..127
    const int tid   = threadIdx.x;
    const int warp  = tid >> 5;          // 0..7
    const int lane  = tid & 31;

    // Select source tensor for this sample (only this one is read)
    const int q  = qual[b];
    const float* __restrict__ src = (q == 1) ? feat : feat_p;
    const int lb = label[b] & 1;   // mask: guaranteed in-bounds gather
    const float* __restrict__ af_pos = avg_feat + (size_t)lb * C_;
    const float* __restrict__ af_neg = avg_feat + (size_t)(1 - lb) * C_;

    // This warp owns 16 contiguous channels: cbase .. cbase+15
    const int cbase = chunk * CPB + warp * 16;
    const float4* __restrict__ base =
        reinterpret_cast<const float4*>(src + ((size_t)b * C_ + cbase) * HW_);

    const bool tail = (lane < VEC_ - 32);   // lanes 0..16 load the second vec

    float acc = 0.0f;

    // 8 iterations, 2 adjacent channels each: sequential forward stream,
    // 4 independent LDG.128 in flight per thread per iteration (R9 body).
    #pragma unroll
    for (int it = 0; it < 8; ++it) {
        const float4* __restrict__ rowA = base + (size_t)(2 * it)     * VEC_;
        const float4* __restrict__ rowB = base + (size_t)(2 * it + 1) * VEC_;

        float4 a0 = rowA[lane];
        float4 b0 = rowB[lane];
        float4 a1, b1;
        if (tail) { a1 = rowA[lane + 32]; b1 = rowB[lane + 32]; }

        float sA = a0.x + a0.y + a0.z + a0.w;
        float sB = b0.x + b0.y + b0.z + b0.w;
        if (tail) {
            sA += a1.x + a1.y + a1.z + a1.w;
            sB += b1.x + b1.y + b1.z + b1.w;
        }
        #pragma unroll
        for (int off = 16; off > 0; off >>= 1) {
            sA += __shfl_xor_sync(0xFFFFFFFFu, sA, off);
            sB += __shfl_xor_sync(0xFFFFFFFFu, sB, off);
        }

        if (lane == 0) {
            const int   c0   = cbase + 2 * it;
            const int   c1   = c0 + 1;
            const float selA = sA * (1.0f / (float)HW_);
            const float selB = sB * (1.0f / (float)HW_);
            acc += fmaxf(fabsf(selA - af_pos[c0] + EPS) - fabsf(selA - af_neg[c0] + EPS) + MARGIN, 0.0f);
            acc += fmaxf(fabsf(selB - af_pos[c1] + EPS) - fabsf(selB - af_neg[c1] + EPS) + MARGIN, 0.0f);
        }
    }

    // Block reduce the 8 warp-leader partials (fixed order -> deterministic)
    __shared__ float warp_acc[8];
    __shared__ bool  is_last;
    if (lane == 0) warp_acc[warp] = acc;
    __syncthreads();
    if (tid == 0) {
        float t = 0.0f;
        #pragma unroll
        for (int w = 0; w < 8; ++w) t += warp_acc[w];
        __stcg(&g_partials[b * CHUNKS + chunk], t * (1.0f / (float)C_));
        __threadfence();
        unsigned int ticket = atomicAdd(&g_ticket, 1u);
        is_last = (ticket == NPART - 1);
    }
    __syncthreads();

    // Last block to finish performs the deterministic final sum.
    if (is_last) {
        if (tid == 0) g_ticket = 0;   // reset for next graph replay
        float s2 = 0.0f;
        #pragma unroll
        for (int i = 0; i < NPART / THREADS; ++i)       // 4 each, fixed order
            s2 += __ldcg(&g_partials[tid + i * THREADS]);

        __shared__ float sm[THREADS];
        sm[tid] = s2;
        __syncthreads();
        #pragma unroll
        for (int step = THREADS / 2; step > 0; step >>= 1) {
            if (tid < step) sm[tid] += sm[tid + step];
            __syncthreads();
        }
        if (tid == 0) out[0] = sm[0];
    }
}

extern "C" void kernel_launch(void* const* d_in, const int* in_sizes, int n_in,
                              void* d_out, int out_size)
{
    const float* feat     = (const float*)d_in[0];
    const float* feat_p   = (const float*)d_in[1];
    const float* avg_feat = (const float*)d_in[2];
    const int*   qual     = (const int*)d_in[3];
    const int*   label    = (const int*)d_in[4];
    float* out = (float*)d_out;

    dim3 grid(CHUNKS, B_);
    ffl_fused_kernel<<<grid, THREADS>>>(feat, feat_p, avg_feat, qual, label, out);
}

// round 15
// speedup vs baseline: 1.6230x; 1.1289x over previous
#include <cuda_runtime.h>
#include <cuda_bf16.h>

// Problem constants (fixed shapes from reference)
#define B_     128
#define C_     1024
#define HW_    196          // 14*14
#define VEC_   49           // 196/4 float4 per channel row
#define CHUNKS 8            // 8*128 = 1024 blocks -> single wave on 148 SMs
#define CPB    128          // channels per block
#define THREADS 256         // 8 warps
#define NPART  (B_*CHUNKS)  // 1024 partials (one per block)

#define MARGIN 1.0f
#define EPS    1e-6f

__device__ float g_partials[NPART];
__device__ unsigned int g_ticket = 0;   // self-resetting; replay-safe

// minBlocks=8 -> 32-reg cap -> full 2048-thread occupancy (measured-best point).
__global__ __launch_bounds__(THREADS, 8)
void ffl_fused_kernel(const float* __restrict__ feat,
                      const float* __restrict__ feat_p,
                      const float* __restrict__ avg_feat,   // [2,1024]
                      const int* __restrict__ qual,         // [128] int32
                      const int* __restrict__ label,        // [128] int32
                      float* __restrict__ out)
{
    const int chunk = blockIdx.x;        // 0..7
    const int b     = blockIdx.y;        // 0..127
    const int tid   = threadIdx.x;
    const int warp  = tid >> 5;          // 0..7
    const int lane  = tid & 31;

    // Per-lane channel partials: [warp][channel-in-warp][lane]
    __shared__ float sm_part[8][16][32];     // 16 KB
    __shared__ float sm_red[CPB];            // per-channel losses
    __shared__ bool  is_last;

    // Select source tensor for this sample (only this one is read)
    const int q  = qual[b];
    const float* __restrict__ src = (q == 1) ? feat : feat_p;
    const int lb = label[b] & 1;   // mask: guaranteed in-bounds gather
    const float* __restrict__ af_pos = avg_feat + (size_t)lb * C_;
    const float* __restrict__ af_neg = avg_feat + (size_t)(1 - lb) * C_;

    // This warp owns 16 contiguous channels: cbase .. cbase+15
    const int cbase = chunk * CPB + warp * 16;
    const float4* __restrict__ base =
        reinterpret_cast<const float4*>(src + ((size_t)b * C_ + cbase) * HW_);

    const bool tail = (lane < VEC_ - 32);   // lanes 0..16 load the second vec

    // ---- Streaming loop: pure LDG -> FADD -> STS, no cross-lane deps ----
    #pragma unroll
    for (int it = 0; it < 8; ++it) {
        const float4* __restrict__ rowA = base + (size_t)(2 * it)     * VEC_;
        const float4* __restrict__ rowB = base + (size_t)(2 * it + 1) * VEC_;

        float4 a0 = rowA[lane];
        float4 b0 = rowB[lane];
        float4 a1, b1;
        if (tail) { a1 = rowA[lane + 32]; b1 = rowB[lane + 32]; }

        float sA = (a0.x + a0.y) + (a0.z + a0.w);
        float sB = (b0.x + b0.y) + (b0.z + b0.w);
        if (tail) {
            sA += (a1.x + a1.y) + (a1.z + a1.w);
            sB += (b1.x + b1.y) + (b1.z + b1.w);
        }
        sm_part[warp][2 * it][lane]     = sA;
        sm_part[warp][2 * it + 1][lane] = sB;
    }
    __syncthreads();

    // ---- Deferred reduction: thread c sums channel c's 32 lane-partials ----
    // Lane-rotated read order -> conflict-free LDS.
    if (tid < CPB) {
        const int w = tid >> 4;
        const int r = tid & 15;
        const int rot = tid & 31;
        float sum = 0.0f;
        #pragma unroll
        for (int j = 0; j < 32; ++j)
            sum += sm_part[w][r][(j + rot) & 31];

        const int   c   = chunk * CPB + tid;    // global channel
        const float sel = sum * (1.0f / (float)HW_);
        sm_red[tid] = fmaxf(fabsf(sel - af_pos[c] + EPS)
                          - fabsf(sel - af_neg[c] + EPS) + MARGIN, 0.0f);
    }
    __syncthreads();

    // ---- Block tree over 128 channel losses (fixed order -> deterministic) ----
    #pragma unroll
    for (int step = CPB / 2; step > 0; step >>= 1) {
        if (tid < step) sm_red[tid] += sm_red[tid + step];
        __syncthreads();
    }

    if (tid == 0) {
        __stcg(&g_partials[b * CHUNKS + chunk], sm_red[0] * (1.0f / (float)C_));
        __threadfence();
        unsigned int ticket = atomicAdd(&g_ticket, 1u);
        is_last = (ticket == NPART - 1);
    }
    __syncthreads();

    // Last block to finish performs the deterministic final sum.
    if (is_last) {
        if (tid == 0) g_ticket = 0;   // reset for next graph replay
        float s2 = 0.0f;
        #pragma unroll
        for (int i = 0; i < NPART / THREADS; ++i)       // 4 each, fixed order
            s2 += __ldcg(&g_partials[tid + i * THREADS]);

        __shared__ float sm[THREADS];
        sm[tid] = s2;
        __syncthreads();
        #pragma unroll
        for (int step = THREADS / 2; step > 0; step >>= 1) {
            if (tid < step) sm[tid] += sm[tid + step];
            __syncthreads();
        }
        if (tid == 0) out[0] = sm[0];
    }
}

extern "C" void kernel_launch(void* const* d_in, const int* in_sizes, int n_in,
                              void* d_out, int out_size)
{
    const float* feat     = (const float*)d_in[0];
    const float* feat_p   = (const float*)d_in[1];
    const float* avg_feat = (const float*)d_in[2];
    const int*   qual     = (const int*)d_in[3];
    const int*   label    = (const int*)d_in[4];
    float* out = (float*)d_out;

    dim3 grid(CHUNKS, B_);
    ffl_fused_kernel<<<grid, THREADS>>>(feat, feat_p, avg_feat, qual, label, out);
}